// round 9
// baseline (speedup 1.0000x reference)
#include <cuda_runtime.h>
#include <cstdint>
#include <math.h>

#define BB 16
#define L_TOTAL 327
#define PROW_PITCH 328
#define S_DIM 256
#define Z_DIM 64
#define S_IN 21
#define PE_DIM 64
#define MAXPOS 104

__constant__ int c_starts[7] = {1, 25, 41, 89, 193, 209, 313};
__constant__ int c_lens[7]   = {24, 16, 48, 104, 16, 104, 14};

// pair_id as 8x8 LUT over (region_i, region_j); cdr3xcdr3 (1,1) fixed up in code.
__constant__ unsigned char c_plut[64] = {
    0, 1, 1, 1, 1, 1, 1, 1,
    1, 3, 4, 4, 4, 4, 4, 4,
    1, 4, 5,11,12,13,14,15,
    1, 4,11, 6,16,17,18,19,
    1, 4,12,16, 7,20,21,22,
    1, 4,13,17,20, 8,23,24,
    1, 4,14,18,21,23, 9,25,
    1, 4,15,19,22,24,25,10
};

// Precomputed scratch (written by setup_kernel)
__device__ float g_pe[MAXPOS * S_DIM];      // PE projection table
__device__ float g_table[32 * 64];          // z vocabulary
__device__ float g_seqWT[S_IN * S_DIM];     // seq_W transposed [d][c]

__device__ __forceinline__ int reg_of(int i) {
    if (i == 0)  return 0;
    if (i < 25)  return 1;
    if (i < 41)  return 2;
    if (i < 89)  return 3;
    if (i < 193) return 4;
    if (i < 209) return 5;
    if (i < 313) return 6;
    return 7;
}

// ---------------- setup kernel ----------------
// blocks [0,104): g_pe rows; block 104: g_table + seq_W transpose
__global__ void __launch_bounds__(256)
setup_kernel(const float* __restrict__ pos_W, const float* __restrict__ pos_b,
             const float* __restrict__ pair1_W, const float* __restrict__ pair1_b,
             const float* __restrict__ pair2_W, const float* __restrict__ pair2_b,
             const float* __restrict__ seq_W)
{
#if __CUDA_ARCH__ >= 900
    cudaTriggerProgrammaticLaunchCompletion();   // let the fused grid launch now
#endif
    const int bid = blockIdx.x;
    const int c   = threadIdx.x;

    if (bid < MAXPOS) {
        __shared__ float4 perow4[PE_DIM / 4];
        const int pos = bid;
        if (c < PE_DIM) {
            float inv = exp2f(-(float)c * (13.287712379549449f / 64.0f));
            float ang = (float)pos * inv;
            ((float*)perow4)[c] = (c & 1) ? cosf(ang) : sinf(ang);
        }
        __syncthreads();
        float pe = pos_b[c];
        const float4* pw = (const float4*)(pos_W + c * PE_DIM);
        float pe1 = 0.f;
        #pragma unroll
        for (int q = 0; q < 16; q += 2) {
            float4 w0 = pw[q],   p0 = perow4[q];
            float4 w1 = pw[q+1], p1 = perow4[q+1];
            pe  = fmaf(p0.x, w0.x, pe);  pe  = fmaf(p0.y, w0.y, pe);
            pe  = fmaf(p0.z, w0.z, pe);  pe  = fmaf(p0.w, w0.w, pe);
            pe1 = fmaf(p1.x, w1.x, pe1); pe1 = fmaf(p1.y, w1.y, pe1);
            pe1 = fmaf(p1.z, w1.z, pe1); pe1 = fmaf(p1.w, w1.w, pe1);
        }
        g_pe[pos * S_DIM + c] = pe + pe1;
    } else {
        for (int idx = c; idx < 32 * 64; idx += 256) {
            int p  = idx >> 6;
            int cc = idx & 63;
            float v;
            if (cc < 32) v = pair1_W[cc * 8 + (p >> 2)] + pair1_b[cc];
            else { int c2 = cc - 32; v = pair2_W[c2 * 4 + (p & 3)] + pair2_b[c2]; }
            g_table[idx] = v;
        }
        // transpose seq_W [256][21] -> g_seqWT [21][256]
        for (int idx = c; idx < S_IN * S_DIM; idx += 256) {
            int d  = idx >> 8;
            int ch = idx & 255;
            g_seqWT[idx] = seq_W[ch * S_IN + d];
        }
    }
}

// ---------------- fused kernel (PDL secondary): one block per (b, i) ----------------
__global__ void __launch_bounds__(256)
fused_kernel(const float* __restrict__ s0, const float* __restrict__ s1,
             const float* __restrict__ s2, const float* __restrict__ s3,
             const float* __restrict__ s4, const float* __restrict__ s5,
             const float* __restrict__ s6,
             const float* __restrict__ seq_b,
             const float* __restrict__ collapse_token,
             const float* __restrict__ collapse_weight,
             const float* __restrict__ region_w,
             float* __restrict__ sout, float* __restrict__ zout)
{
    __shared__ float4 table[32 * 16];
    __shared__ unsigned char prow[PROW_PITCH];
    __shared__ float srow[24];

    const int bl = blockIdx.x;                     // b * L_TOTAL + i
    const int i  = bl % L_TOTAL;
    const int b  = bl / L_TOTAL;
    const int c  = threadIdx.x;

    // --- pre-sync: independent of setup_kernel outputs ---
    const int ri = reg_of(i);
    for (int j = c; j < L_TOTAL; j += 256) {
        int rj = reg_of(j);
        int p  = c_plut[ri * 8 + rj];
        if (ri == 1 && rj == 1) {                  // cdr3 x cdr3 fix-up
            int d = (i > j) ? (i - j) : (j - i);
            p = (i == j) ? 0 : ((d == 1) ? 2 : 3);
        }
        prow[j] = (unsigned char)p;
    }

    int k = 0, pos = 0;
    if (i > 0) {
        k   = ri - 1;
        pos = i - c_starts[k];
        const float* seqp;
        switch (k) {
            case 0: seqp = s0; break;
            case 1: seqp = s1; break;
            case 2: seqp = s2; break;
            case 3: seqp = s3; break;
            case 4: seqp = s4; break;
            case 5: seqp = s5; break;
            default: seqp = s6; break;
        }
        if (c < S_IN)
            srow[c] = seqp[((size_t)b * c_lens[k] + pos) * S_IN + c];
    }

#if __CUDA_ARCH__ >= 900
    cudaGridDependencySynchronize();               // wait for setup_kernel results
#endif

    // --- post-sync: copy z table from L2 ---
    {
        const float4* gt = (const float4*)g_table;
        table[c]       = gt[c];
        table[c + 256] = gt[c + 256];
    }
    __syncthreads();

    // ---- s row ----
    float* orow = sout + (size_t)bl * S_DIM;
    if (i == 0) {
        orow[c] = collapse_weight[0] * collapse_token[c];
    } else {
        float se = seq_b[c];
        #pragma unroll
        for (int d = 0; d < S_IN; d++)              // coalesced: [d][c] layout
            se = fmaf(srow[d], g_seqWT[d * S_DIM + c], se);
        float pe = g_pe[pos * S_DIM + c];
        orow[c] = region_w[2 * k] * se + region_w[2 * k + 1] * pe;
    }

    // ---- z row: stream 327*16 float4 streaming stores ----
    float4* zrow = (float4*)zout + (size_t)bl * (L_TOTAL * (Z_DIM / 4));
    const int total = L_TOTAL * (Z_DIM / 4);       // 5232
    #pragma unroll 4
    for (int v = c; v < total; v += 256) {
        int j = v >> 4;
        __stcs(&zrow[v], table[((int)prow[j] << 4) + (v & 15)]);
    }
}

extern "C" void kernel_launch(void* const* d_in, const int* in_sizes, int n_in,
                              void* d_out, int out_size)
{
    (void)in_sizes; (void)n_in; (void)out_size;
    // 0..6 region seqs, 7 seq_W, 8 seq_b, 9 pos_W, 10 pos_b, 11 pair1_W, 12 pair1_b,
    // 13 pair2_W, 14 pair2_b, 15 collapse_token, 16 collapse_weight, 17 region_w,
    // 18..24 masks (unused)
    float* out  = (float*)d_out;
    float* zout = out + (size_t)BB * L_TOTAL * S_DIM;   // z follows s

    setup_kernel<<<MAXPOS + 1, 256>>>(
        (const float*)d_in[9],  (const float*)d_in[10],
        (const float*)d_in[11], (const float*)d_in[12],
        (const float*)d_in[13], (const float*)d_in[14],
        (const float*)d_in[7]);

    // PDL launch: fused launches while setup runs; device-side sync gates table reads.
    {
        cudaLaunchConfig_t cfg = {};
        cfg.gridDim  = dim3(BB * L_TOTAL);
        cfg.blockDim = dim3(256);
        cfg.dynamicSmemBytes = 0;
        cudaLaunchAttribute attr[1];
        attr[0].id = cudaLaunchAttributeProgrammaticStreamSerialization;
        attr[0].val.programmaticStreamSerializationAllowed = 1;
        cfg.attrs = attr;
        cfg.numAttrs = 1;

        const float* a0  = (const float*)d_in[0];
        const float* a1  = (const float*)d_in[1];
        const float* a2  = (const float*)d_in[2];
        const float* a3  = (const float*)d_in[3];
        const float* a4  = (const float*)d_in[4];
        const float* a5  = (const float*)d_in[5];
        const float* a6  = (const float*)d_in[6];
        const float* sb  = (const float*)d_in[8];
        const float* ct  = (const float*)d_in[15];
        const float* cw  = (const float*)d_in[16];
        const float* rw  = (const float*)d_in[17];

        cudaLaunchKernelEx(&cfg, fused_kernel,
                           a0, a1, a2, a3, a4, a5, a6,
                           sb, ct, cw, rw, out, zout);
    }
}